// round 16
// baseline (speedup 1.0000x reference)
#include <cuda_runtime.h>
#include <cstdint>

#define NS   8192
#define MD   64
#define AD   2048
#define NT   256

typedef unsigned long long u64;

// ---- device-global scratch (static __device__ arrays: sanctioned) ----
__device__ __align__(16) float2 d_Wint [MD * AD];     // 1 MB  (re,im), [m][a]
__device__ __align__(16) float2 d_WintT[AD * MD];     // 1 MB  (re,im), [a][m]
__device__ __align__(16) float2 d_G[(size_t)AD * AD]; // 32 MB Gram G[a][b]
__device__ __align__(16) float2 d_S[(size_t)NS * AD]; // 128 MB scores

// ---- packed f32x2 helpers ----
__device__ __forceinline__ u64 pk2(float lo, float hi) {
    u64 r; asm("mov.b64 %0,{%1,%2};" : "=l"(r) : "f"(lo), "f"(hi)); return r;
}
__device__ __forceinline__ void upk2(u64 v, float& lo, float& hi) {
    asm("mov.b64 {%0,%1},%2;" : "=f"(lo), "=f"(hi) : "l"(v));
}
__device__ __forceinline__ u64 fma2(u64 a, u64 b, u64 c) {
    u64 d; asm("fma.rn.f32x2 %0,%1,%2,%3;" : "=l"(d) : "l"(a), "l"(b), "l"(c)); return d;
}
// streaming (evict-first) 16B load for one-shot data
__device__ __forceinline__ ulonglong2 ldcs_u64x2(const ulonglong2* p) {
    ulonglong2 v;
    asm("ld.global.cs.v2.u64 {%0,%1},[%2];" : "=l"(v.x), "=l"(v.y) : "l"(p));
    return v;
}

// ============================================================
// k_pad: empty kernels to steer ncu's -s 5 -c 1 capture window
// onto k_prep (launch index 3 of 6; captured = 15 mod 6 = 3).
// ============================================================
__global__ void k_pad() {}

// ============================================================
// k0: interleave + transpose W via smem tile (coalesced both ways)
// 256 CTAs x 256 thr; CTA handles 8 atoms x all 64 m.
// ============================================================
__global__ void k_interleave(const float* __restrict__ Wre,
                             const float* __restrict__ Wim) {
    __shared__ float2 tile[8][65];
    int a0 = blockIdx.x * 8;
    int t = threadIdx.x;
    for (int i = t; i < MD * 8; i += NT) {
        int m = i >> 3, al = i & 7;
        float2 w = make_float2(Wre[m * AD + a0 + al], Wim[m * AD + a0 + al]);
        d_Wint[m * AD + a0 + al] = w;
        tile[al][m] = w;
    }
    __syncthreads();
    for (int i = t; i < 8 * MD; i += NT) {
        int al = i >> 6, m = i & 63;
        d_WintT[(size_t)(a0 + al) * MD + m] = tile[al][m];
    }
}

// ============================================================
// k_prep: fused Scoring + Gram in one launch.
//   bx <  512  : score  S[row][a] for 16 rows   (long CTAs first)
//   bx >= 512  : gram   16a x 128b tile          (2048 short CTAs pack tail)
// ============================================================
#define RPC2       16
#define GRID_SCORE 512
#define GRID_GRAM  2048
#define GRID_PREP  (GRID_SCORE + GRID_GRAM)
#define SMEM_PREP  16384

__global__ __launch_bounds__(NT, 2) void k_prep(const float* __restrict__ xre,
                                                const float* __restrict__ xim) {
    extern __shared__ char smem[];
    int t = threadIdx.x, warp = t >> 5, lane = t & 31;
    int bx = blockIdx.x;
    const u64* Wu = (const u64*)d_Wint;

    if (bx < GRID_SCORE) {
        // ---------------- SCORE branch ----------------
        float2* sh_rr = (float2*)smem;                 // [m][16] (re,re)
        float2* sh_ri = (float2*)(smem + 8192);        // [m][16] (im,im)
        int row0 = bx * RPC2;

        #pragma unroll
        for (int q = 0; q < (RPC2 * MD) / NT; q++) {
            int i = t + q * NT;
            int m = i & 63, row = i >> 6;
            float re = xre[(row0 + row) * MD + m];
            float im = xim[(row0 + row) * MD + m];
            sh_rr[m * RPC2 + row] = make_float2(re, re);
            sh_ri[m * RPC2 + row] = make_float2(im, im);
        }
        __syncthreads();

        const ulonglong2* rr2 = (const ulonglong2*)sh_rr;   // [m*8 + pair]
        const ulonglong2* ri2 = (const ulonglong2*)sh_ri;

        for (int c = 0; c < 8; c++) {
            const int A = c * 256 + warp * 32 + lane;
            u64 a1[RPC2], a2[RPC2];
            #pragma unroll
            for (int r = 0; r < RPC2; r++) { a1[r] = 0ull; a2[r] = 0ull; }

            // depth-2 rolling prefetch of w
            u64 w0 = Wu[0 * AD + A];
            u64 w1 = Wu[1 * AD + A];
            #pragma unroll 2
            for (int m = 0; m < MD; m++) {
                u64 wc = w0;
                w0 = w1;
                if (m < MD - 2) w1 = Wu[(m + 2) * AD + A];
                #pragma unroll
                for (int p = 0; p < 8; p++) {
                    ulonglong2 rp = rr2[m * 8 + p];
                    ulonglong2 ip = ri2[m * 8 + p];
                    a1[2 * p]     = fma2(wc, rp.x, a1[2 * p]);
                    a2[2 * p]     = fma2(wc, ip.x, a2[2 * p]);
                    a1[2 * p + 1] = fma2(wc, rp.y, a1[2 * p + 1]);
                    a2[2 * p + 1] = fma2(wc, ip.y, a2[2 * p + 1]);
                }
            }
            #pragma unroll
            for (int r = 0; r < RPC2; r++) {
                float l1, h1, l2, h2;
                upk2(a1[r], l1, h1); upk2(a2[r], l2, h2);
                // s_re = r_re*w_re + r_im*w_im ; s_im = r_im*w_re - r_re*w_im
                d_S[(size_t)(row0 + r) * AD + A] = make_float2(l1 + h2, l2 - h1);
            }
        }
    } else {
        // ---------------- GRAM branch: 16a x 128b tile ----------------
        int g = bx - GRID_SCORE;                       // 0..2047
        int a0 = (g >> 4) * 16, b0 = (g & 15) * 128;

        float2* sh_ar = (float2*)smem;                 // [m][16] (a_re,a_re)
        float2* sh_ai = (float2*)(smem + 8192);        // [m][16] (a_im,a_im)

        for (int i = t; i < MD * 16; i += NT) {
            int m = i >> 4, a = i & 15;
            float2 w = d_Wint[m * AD + a0 + a];
            sh_ar[m * 16 + a] = make_float2(w.x, w.x);
            sh_ai[m * 16 + a] = make_float2(w.y, w.y);
        }
        __syncthreads();

        const ulonglong2* rr = (const ulonglong2*)sh_ar;   // [m*8 + pair]
        const ulonglong2* ri = (const ulonglong2*)sh_ai;
        const int bb = b0 + lane;

        u64 a1[2][4], a2[2][4];
        #pragma unroll
        for (int r = 0; r < 2; r++)
            #pragma unroll
            for (int j = 0; j < 4; j++) { a1[r][j] = 0ull; a2[r][j] = 0ull; }

        #pragma unroll 4
        for (int m = 0; m < MD; m++) {
            u64 wv[4];
            #pragma unroll
            for (int j = 0; j < 4; j++) wv[j] = Wu[m * AD + bb + 32 * j];
            ulonglong2 rA = rr[m * 8 + warp];   // rows (2w, 2w+1) (re,re)
            ulonglong2 iA = ri[m * 8 + warp];
            #pragma unroll
            for (int r = 0; r < 2; r++) {
                u64 ar = r ? rA.y : rA.x;
                u64 ai = r ? iA.y : iA.x;
                #pragma unroll
                for (int j = 0; j < 4; j++) {
                    a1[r][j] = fma2(wv[j], ar, a1[r][j]);
                    a2[r][j] = fma2(wv[j], ai, a2[r][j]);
                }
            }
        }
        #pragma unroll
        for (int r = 0; r < 2; r++)
            #pragma unroll
            for (int j = 0; j < 4; j++) {
                float l1, h1, l2, h2;
                upk2(a1[r][j], l1, h1); upk2(a2[r][j], l2, h2);
                d_G[(size_t)(a0 + 2 * warp + r) * AD + (bb + 32 * j)] =
                    make_float2(l1 + h2, l2 - h1);
            }
    }
}

// ============================================================
// k_mp: MP iterations. ONE row per 128-thread CTA (4 warps).
// S row (2048 atoms = 1024 pairs) in regs: 8 pairs/thread.
// (round-13/15 proven configuration; S loaded evict-first)
// ============================================================
#define MPT 128
__global__ __launch_bounds__(MPT, 7) void k_mp(const float* __restrict__ xre,
                                               const float* __restrict__ xim,
                                               const int* __restrict__ kp,
                                               float* __restrict__ out,
                                               int out_size) {
    __shared__ float4 red[2][4];

    int t = threadIdx.x, warp = t >> 5, lane = t & 31;
    const size_t row = blockIdx.x;
    const int k = kp[0];

    // load score row: pair pr = j*128 + t  -> atoms (2pr, 2pr+1)
    const ulonglong2* srow = (const ulonglong2*)(d_S + row * AD);
    ulonglong2 s[8];
    #pragma unroll
    for (int j = 0; j < 8; j++) s[j] = ldcs_u64x2(srow + j * MPT + t);

    // residual coefficient: m = t & 63 (threads 64..127 mirror, discarded at write)
    const int m = t & 63;
    const long long gbase = (long long)row * MD;
    const float x0r = xre[gbase + m], x0i = xim[gbase + m];
    float resr = x0r, resi = x0i;

    int cix = 0; float cvr = 0.f, cvi = 0.f;

    for (int it = 0; it < k; it++) {
        float nm2 = -1.f; int nix = 0; float nvr = 0.f, nvi = 0.f;

        if (it == 0) {
            #pragma unroll
            for (int j = 0; j < 8; j++) {
                int p = j * MPT + t;
                float r0, i0, r1, i1;
                upk2(s[j].x, r0, i0); upk2(s[j].y, r1, i1);
                float m2a = fmaf(r0, r0, i0 * i0);
                float m2b = fmaf(r1, r1, i1 * i1);
                if (m2a > nm2) { nm2 = m2a; nix = 2 * p;     nvr = r0; nvi = i0; }
                if (m2b > nm2) { nm2 = m2b; nix = 2 * p + 1; nvr = r1; nvi = i1; }
            }
        } else {
            const float4* grow = (const float4*)(d_G + (size_t)cix * AD);
            const u64 c1 = pk2(-cvr, -cvr);
            const u64 c2 = pk2(cvi, -cvi);
            #pragma unroll
            for (int j = 0; j < 8; j++) {
                int p = j * MPT + t;
                float4 q = grow[p];                 // (g0re,g0im,g1re,g1im)
                u64 g0 = pk2(q.x, q.y), g0s = pk2(q.y, q.x);
                u64 g1 = pk2(q.z, q.w), g1s = pk2(q.w, q.z);
                u64 s0 = fma2(g0, c1, fma2(g0s, c2, s[j].x));
                u64 s1 = fma2(g1, c1, fma2(g1s, c2, s[j].y));
                s[j] = make_ulonglong2(s0, s1);
                float r0, i0, r1, i1;
                upk2(s0, r0, i0); upk2(s1, r1, i1);
                float m2a = fmaf(r0, r0, i0 * i0);
                float m2b = fmaf(r1, r1, i1 * i1);
                if (m2a > nm2) { nm2 = m2a; nix = 2 * p;     nvr = r0; nvi = i0; }
                if (m2b > nm2) { nm2 = m2b; nix = 2 * p + 1; nvr = r1; nvi = i1; }
            }
        }

        // warp reduce (tie -> smallest atom index)
        #pragma unroll
        for (int o = 16; o > 0; o >>= 1) {
            float om  = __shfl_xor_sync(0xffffffffu, nm2, o);
            int   oi  = __shfl_xor_sync(0xffffffffu, nix, o);
            float ovr = __shfl_xor_sync(0xffffffffu, nvr, o);
            float ovi = __shfl_xor_sync(0xffffffffu, nvi, o);
            if (om > nm2 || (om == nm2 && oi < nix)) { nm2 = om; nix = oi; nvr = ovr; nvi = ovi; }
        }
        int par = it & 1;
        if (lane == 0)
            red[par][warp] = make_float4(nm2, __int_as_float(nix), nvr, nvi);
        __syncthreads();

        // combine 4 warp candidates (deterministic, all threads identical)
        float  bm = -1.f; int bi = 0; float bvr = 0.f, bvi = 0.f;
        #pragma unroll
        for (int w = 0; w < 4; w++) {
            float4 cd = red[par][w];
            int ci = __float_as_int(cd.y);
            if (cd.x > bm || (cd.x == bm && ci < bi)) {
                bm = cd.x; bi = ci; bvr = cd.z; bvi = cd.w;
            }
        }
        cix = bi; cvr = bvr; cvi = bvi;

        // residual update for own m
        float2 w = d_WintT[(size_t)cix * MD + m];
        resr -= cvr * w.x - cvi * w.y;
        resi -= cvr * w.y + cvi * w.x;
    }

    // ---- outputs (planar4 validated; real2 fallback) ----
    if (t < MD) {
        const long long NM = (long long)NS * MD;
        if ((long long)out_size >= 4 * NM) {
            out[gbase + m]          = resr;
            out[NM + gbase + m]     = resi;
            out[2 * NM + gbase + m] = x0r - resr;
            out[3 * NM + gbase + m] = x0i - resi;
        } else if ((long long)out_size >= 2 * NM) {
            out[gbase + m]      = resr;
            out[NM + gbase + m] = x0r - resr;
        }
    }
}

extern "C" void kernel_launch(void* const* d_in, const int* in_sizes, int n_in,
                              void* d_out, int out_size) {
    const float* xre = (const float*)d_in[0];
    const float* xim = (const float*)d_in[1];
    const float* Wre = (const float*)d_in[2];
    const float* Wim = (const float*)d_in[3];
    const int*   kp  = (const int*)d_in[4];

    // Launch order chosen so ncu (-s 5 -c 1, capture index = 15 mod 6 = 3)
    // lands on k_prep:  0=pad, 1=pad, 2=interleave, 3=PREP, 4=mp, 5=pad
    k_pad<<<1, 32>>>();
    k_pad<<<1, 32>>>();

    k_interleave<<<AD / 8, NT>>>(Wre, Wim);

    cudaFuncSetAttribute(k_prep, cudaFuncAttributeMaxDynamicSharedMemorySize,
                         SMEM_PREP);
    k_prep<<<GRID_PREP, NT, SMEM_PREP>>>(xre, xim);

    k_mp<<<NS, MPT>>>(xre, xim, kp, (float*)d_out, out_size);

    k_pad<<<1, 32>>>();
}

// round 17
// speedup vs baseline: 1.1114x; 1.1114x over previous
#include <cuda_runtime.h>
#include <cstdint>

#define NS   8192
#define MD   64
#define AD   2048
#define NT   256

typedef unsigned long long u64;

// ---- device-global scratch (static __device__ arrays: sanctioned) ----
__device__ __align__(16) float2 d_Wint [MD * AD];     // 1 MB  (re,im), [m][a]
__device__ __align__(16) float2 d_WintT[AD * MD];     // 1 MB  (re,im), [a][m]
__device__ __align__(16) float2 d_G[(size_t)AD * AD]; // 32 MB Gram G[a][b]
__device__ __align__(16) float2 d_S[(size_t)NS * AD]; // 128 MB scores

// ---- packed f32x2 helpers ----
__device__ __forceinline__ u64 pk2(float lo, float hi) {
    u64 r; asm("mov.b64 %0,{%1,%2};" : "=l"(r) : "f"(lo), "f"(hi)); return r;
}
__device__ __forceinline__ void upk2(u64 v, float& lo, float& hi) {
    asm("mov.b64 {%0,%1},%2;" : "=f"(lo), "=f"(hi) : "l"(v));
}
__device__ __forceinline__ u64 fma2(u64 a, u64 b, u64 c) {
    u64 d; asm("fma.rn.f32x2 %0,%1,%2,%3;" : "=l"(d) : "l"(a), "l"(b), "l"(c)); return d;
}
// streaming (evict-first) 16B load for one-shot data
__device__ __forceinline__ ulonglong2 ldcs_u64x2(const ulonglong2* p) {
    ulonglong2 v;
    asm("ld.global.cs.v2.u64 {%0,%1},[%2];" : "=l"(v.x), "=l"(v.y) : "l"(p));
    return v;
}

// ============================================================
// k_pad: empty kernels to steer ncu's -s 5 -c 1 capture window
// onto k_prep (launch index 3 of 6; captured = 15 mod 6 = 3).
// ============================================================
__global__ void k_pad() {}

// ============================================================
// k0: interleave + transpose W via smem tile (coalesced both ways)
// 256 CTAs x 256 thr; CTA handles 8 atoms x all 64 m.
// ============================================================
__global__ void k_interleave(const float* __restrict__ Wre,
                             const float* __restrict__ Wim) {
    __shared__ float2 tile[8][65];
    int a0 = blockIdx.x * 8;
    int t = threadIdx.x;
    for (int i = t; i < MD * 8; i += NT) {
        int m = i >> 3, al = i & 7;
        float2 w = make_float2(Wre[m * AD + a0 + al], Wim[m * AD + a0 + al]);
        d_Wint[m * AD + a0 + al] = w;
        tile[al][m] = w;
    }
    __syncthreads();
    for (int i = t; i < 8 * MD; i += NT) {
        int al = i >> 6, m = i & 63;
        d_WintT[(size_t)(a0 + al) * MD + m] = tile[al][m];
    }
}

// ============================================================
// k_prep: fused Scoring + Gram in one launch.
//   bx <  1024 : score  S[row][a] for 8 rows, 2 atoms/thread
//   bx >= 1024 : gram   16a x 128b tile (2048 short CTAs pack tail)
// ============================================================
#define RPC2       8
#define GRID_SCORE (NS / RPC2)          // 1024
#define GRID_GRAM  2048
#define GRID_PREP  (GRID_SCORE + GRID_GRAM)
#define SMEM_PREP  16384

__global__ __launch_bounds__(NT, 2) void k_prep(const float* __restrict__ xre,
                                                const float* __restrict__ xim) {
    extern __shared__ char smem[];
    int t = threadIdx.x, warp = t >> 5, lane = t & 31;
    int bx = blockIdx.x;
    const u64* Wu = (const u64*)d_Wint;

    if (bx < GRID_SCORE) {
        // ---------------- SCORE branch: 8 rows, 2 atoms/thread ----------------
        float2* sh_rr = (float2*)smem;                 // [m][8] (re,re)
        float2* sh_ri = (float2*)(smem + 4096);        // [m][8] (im,im)
        int row0 = bx * RPC2;

        #pragma unroll
        for (int q = 0; q < (RPC2 * MD) / NT; q++) {
            int i = t + q * NT;                        // 0..511
            int m = i & 63, row = i >> 6;              // row 0..7
            float re = xre[(row0 + row) * MD + m];
            float im = xim[(row0 + row) * MD + m];
            sh_rr[m * RPC2 + row] = make_float2(re, re);
            sh_ri[m * RPC2 + row] = make_float2(im, im);
        }
        __syncthreads();

        const ulonglong2* rr2 = (const ulonglong2*)sh_rr;   // [m*4 + pair]
        const ulonglong2* ri2 = (const ulonglong2*)sh_ri;

        for (int c = 0; c < 4; c++) {
            const int A0 = c * 256 + warp * 32 + lane;  // atom stream 0
            const int A1 = A0 + 1024;                   // atom stream 1
            u64 a1[2][RPC2], a2[2][RPC2];
            #pragma unroll
            for (int u = 0; u < 2; u++)
                #pragma unroll
                for (int r = 0; r < RPC2; r++) { a1[u][r] = 0ull; a2[u][r] = 0ull; }

            // depth-2 rolling prefetch of both w streams
            u64 wA0 = Wu[0 * AD + A0], wB0 = Wu[0 * AD + A1];
            u64 wA1 = Wu[1 * AD + A0], wB1 = Wu[1 * AD + A1];
            #pragma unroll 2
            for (int m = 0; m < MD; m++) {
                u64 wA = wA0, wB = wB0;
                wA0 = wA1; wB0 = wB1;
                if (m < MD - 2) {
                    wA1 = Wu[(m + 2) * AD + A0];
                    wB1 = Wu[(m + 2) * AD + A1];
                }
                #pragma unroll
                for (int p = 0; p < 4; p++) {           // 4 LDS pairs = 8 rows
                    ulonglong2 rp = rr2[m * 4 + p];
                    ulonglong2 ip = ri2[m * 4 + p];
                    a1[0][2 * p]     = fma2(wA, rp.x, a1[0][2 * p]);
                    a2[0][2 * p]     = fma2(wA, ip.x, a2[0][2 * p]);
                    a1[0][2 * p + 1] = fma2(wA, rp.y, a1[0][2 * p + 1]);
                    a2[0][2 * p + 1] = fma2(wA, ip.y, a2[0][2 * p + 1]);
                    a1[1][2 * p]     = fma2(wB, rp.x, a1[1][2 * p]);
                    a2[1][2 * p]     = fma2(wB, ip.x, a2[1][2 * p]);
                    a1[1][2 * p + 1] = fma2(wB, rp.y, a1[1][2 * p + 1]);
                    a2[1][2 * p + 1] = fma2(wB, ip.y, a2[1][2 * p + 1]);
                }
            }
            #pragma unroll
            for (int u = 0; u < 2; u++) {
                int A = u ? A1 : A0;
                #pragma unroll
                for (int r = 0; r < RPC2; r++) {
                    float l1, h1, l2, h2;
                    upk2(a1[u][r], l1, h1); upk2(a2[u][r], l2, h2);
                    // s_re = r_re*w_re + r_im*w_im ; s_im = r_im*w_re - r_re*w_im
                    d_S[(size_t)(row0 + r) * AD + A] = make_float2(l1 + h2, l2 - h1);
                }
            }
        }
    } else {
        // ---------------- GRAM branch: 16a x 128b tile ----------------
        int g = bx - GRID_SCORE;                       // 0..2047
        int a0 = (g >> 4) * 16, b0 = (g & 15) * 128;

        float2* sh_ar = (float2*)smem;                 // [m][16] (a_re,a_re)
        float2* sh_ai = (float2*)(smem + 8192);        // [m][16] (a_im,a_im)

        for (int i = t; i < MD * 16; i += NT) {
            int m = i >> 4, a = i & 15;
            float2 w = d_Wint[m * AD + a0 + a];
            sh_ar[m * 16 + a] = make_float2(w.x, w.x);
            sh_ai[m * 16 + a] = make_float2(w.y, w.y);
        }
        __syncthreads();

        const ulonglong2* rr = (const ulonglong2*)sh_ar;   // [m*8 + pair]
        const ulonglong2* ri = (const ulonglong2*)sh_ai;
        const int bb = b0 + lane;

        u64 a1[2][4], a2[2][4];
        #pragma unroll
        for (int r = 0; r < 2; r++)
            #pragma unroll
            for (int j = 0; j < 4; j++) { a1[r][j] = 0ull; a2[r][j] = 0ull; }

        #pragma unroll 4
        for (int m = 0; m < MD; m++) {
            u64 wv[4];
            #pragma unroll
            for (int j = 0; j < 4; j++) wv[j] = Wu[m * AD + bb + 32 * j];
            ulonglong2 rA = rr[m * 8 + warp];   // rows (2w, 2w+1) (re,re)
            ulonglong2 iA = ri[m * 8 + warp];
            #pragma unroll
            for (int r = 0; r < 2; r++) {
                u64 ar = r ? rA.y : rA.x;
                u64 ai = r ? iA.y : iA.x;
                #pragma unroll
                for (int j = 0; j < 4; j++) {
                    a1[r][j] = fma2(wv[j], ar, a1[r][j]);
                    a2[r][j] = fma2(wv[j], ai, a2[r][j]);
                }
            }
        }
        #pragma unroll
        for (int r = 0; r < 2; r++)
            #pragma unroll
            for (int j = 0; j < 4; j++) {
                float l1, h1, l2, h2;
                upk2(a1[r][j], l1, h1); upk2(a2[r][j], l2, h2);
                d_G[(size_t)(a0 + 2 * warp + r) * AD + (bb + 32 * j)] =
                    make_float2(l1 + h2, l2 - h1);
            }
    }
}

// ============================================================
// k_mp: MP iterations. ONE row per 128-thread CTA (4 warps).
// S row (2048 atoms = 1024 pairs) in regs: 8 pairs/thread.
// (round-13/15 proven configuration; S loaded evict-first)
// ============================================================
#define MPT 128
__global__ __launch_bounds__(MPT, 7) void k_mp(const float* __restrict__ xre,
                                               const float* __restrict__ xim,
                                               const int* __restrict__ kp,
                                               float* __restrict__ out,
                                               int out_size) {
    __shared__ float4 red[2][4];

    int t = threadIdx.x, warp = t >> 5, lane = t & 31;
    const size_t row = blockIdx.x;
    const int k = kp[0];

    // load score row: pair pr = j*128 + t  -> atoms (2pr, 2pr+1)
    const ulonglong2* srow = (const ulonglong2*)(d_S + row * AD);
    ulonglong2 s[8];
    #pragma unroll
    for (int j = 0; j < 8; j++) s[j] = ldcs_u64x2(srow + j * MPT + t);

    // residual coefficient: m = t & 63 (threads 64..127 mirror, discarded at write)
    const int m = t & 63;
    const long long gbase = (long long)row * MD;
    const float x0r = xre[gbase + m], x0i = xim[gbase + m];
    float resr = x0r, resi = x0i;

    int cix = 0; float cvr = 0.f, cvi = 0.f;

    for (int it = 0; it < k; it++) {
        float nm2 = -1.f; int nix = 0; float nvr = 0.f, nvi = 0.f;

        if (it == 0) {
            #pragma unroll
            for (int j = 0; j < 8; j++) {
                int p = j * MPT + t;
                float r0, i0, r1, i1;
                upk2(s[j].x, r0, i0); upk2(s[j].y, r1, i1);
                float m2a = fmaf(r0, r0, i0 * i0);
                float m2b = fmaf(r1, r1, i1 * i1);
                if (m2a > nm2) { nm2 = m2a; nix = 2 * p;     nvr = r0; nvi = i0; }
                if (m2b > nm2) { nm2 = m2b; nix = 2 * p + 1; nvr = r1; nvi = i1; }
            }
        } else {
            const float4* grow = (const float4*)(d_G + (size_t)cix * AD);
            const u64 c1 = pk2(-cvr, -cvr);
            const u64 c2 = pk2(cvi, -cvi);
            #pragma unroll
            for (int j = 0; j < 8; j++) {
                int p = j * MPT + t;
                float4 q = grow[p];                 // (g0re,g0im,g1re,g1im)
                u64 g0 = pk2(q.x, q.y), g0s = pk2(q.y, q.x);
                u64 g1 = pk2(q.z, q.w), g1s = pk2(q.w, q.z);
                u64 s0 = fma2(g0, c1, fma2(g0s, c2, s[j].x));
                u64 s1 = fma2(g1, c1, fma2(g1s, c2, s[j].y));
                s[j] = make_ulonglong2(s0, s1);
                float r0, i0, r1, i1;
                upk2(s0, r0, i0); upk2(s1, r1, i1);
                float m2a = fmaf(r0, r0, i0 * i0);
                float m2b = fmaf(r1, r1, i1 * i1);
                if (m2a > nm2) { nm2 = m2a; nix = 2 * p;     nvr = r0; nvi = i0; }
                if (m2b > nm2) { nm2 = m2b; nix = 2 * p + 1; nvr = r1; nvi = i1; }
            }
        }

        // warp reduce (tie -> smallest atom index)
        #pragma unroll
        for (int o = 16; o > 0; o >>= 1) {
            float om  = __shfl_xor_sync(0xffffffffu, nm2, o);
            int   oi  = __shfl_xor_sync(0xffffffffu, nix, o);
            float ovr = __shfl_xor_sync(0xffffffffu, nvr, o);
            float ovi = __shfl_xor_sync(0xffffffffu, nvi, o);
            if (om > nm2 || (om == nm2 && oi < nix)) { nm2 = om; nix = oi; nvr = ovr; nvi = ovi; }
        }
        int par = it & 1;
        if (lane == 0)
            red[par][warp] = make_float4(nm2, __int_as_float(nix), nvr, nvi);
        __syncthreads();

        // combine 4 warp candidates (deterministic, all threads identical)
        float  bm = -1.f; int bi = 0; float bvr = 0.f, bvi = 0.f;
        #pragma unroll
        for (int w = 0; w < 4; w++) {
            float4 cd = red[par][w];
            int ci = __float_as_int(cd.y);
            if (cd.x > bm || (cd.x == bm && ci < bi)) {
                bm = cd.x; bi = ci; bvr = cd.z; bvi = cd.w;
            }
        }
        cix = bi; cvr = bvr; cvi = bvi;

        // residual update for own m
        float2 w = d_WintT[(size_t)cix * MD + m];
        resr -= cvr * w.x - cvi * w.y;
        resi -= cvr * w.y + cvi * w.x;
    }

    // ---- outputs (planar4 validated; real2 fallback) ----
    if (t < MD) {
        const long long NM = (long long)NS * MD;
        if ((long long)out_size >= 4 * NM) {
            out[gbase + m]          = resr;
            out[NM + gbase + m]     = resi;
            out[2 * NM + gbase + m] = x0r - resr;
            out[3 * NM + gbase + m] = x0i - resi;
        } else if ((long long)out_size >= 2 * NM) {
            out[gbase + m]      = resr;
            out[NM + gbase + m] = x0r - resr;
        }
    }
}

extern "C" void kernel_launch(void* const* d_in, const int* in_sizes, int n_in,
                              void* d_out, int out_size) {
    const float* xre = (const float*)d_in[0];
    const float* xim = (const float*)d_in[1];
    const float* Wre = (const float*)d_in[2];
    const float* Wim = (const float*)d_in[3];
    const int*   kp  = (const int*)d_in[4];

    // Launch order chosen so ncu (-s 5 -c 1, capture index = 15 mod 6 = 3)
    // lands on k_prep:  0=pad, 1=pad, 2=interleave, 3=PREP, 4=mp, 5=pad
    k_pad<<<1, 32>>>();
    k_pad<<<1, 32>>>();

    k_interleave<<<AD / 8, NT>>>(Wre, Wim);

    cudaFuncSetAttribute(k_prep, cudaFuncAttributeMaxDynamicSharedMemorySize,
                         SMEM_PREP);
    k_prep<<<GRID_PREP, NT, SMEM_PREP>>>(xre, xim);

    k_mp<<<NS, MPT>>>(xre, xim, kp, (float*)d_out, out_size);

    k_pad<<<1, 32>>>();
}